// round 6
// baseline (speedup 1.0000x reference)
#include <cuda_runtime.h>
#include <cuda_bf16.h>
#include <math.h>

#define N_SESS   4096
#define T_TRIALS 2048

// Warp-per-session affine scan, 8 trials/lane (chunk = 256 trials, 8 chunks).
//  - halved shuffle-scan count vs 4-trials/lane (the serial bottleneck)
//  - coefficients via SEL from 8 precomputed constants (inputs are exact {0,1})
//  - next chunk's 6 float4 loads issued before the warp scan (latency overlap)
__global__ __launch_bounds__(128) void qvalue_kernel(
    const float* __restrict__ inp,    // (B, T, 3)
    const float* __restrict__ araw,   // (4,)
    const float* __restrict__ kv,     // (4,)
    float* __restrict__ out)          // (B, T, 2)
{
    const int gtid = blockIdx.x * blockDim.x + threadIdx.x;
    const int warp = gtid >> 5;
    const int lane = gtid & 31;
    if (warp >= N_SESS) return;

    // am[i] = 1 - sigmoid(araw[i]),  ak[i] = sigmoid(araw[i]) * k[i]
    float am[4], ak[4];
#pragma unroll
    for (int i = 0; i < 4; i++) {
        float s = 1.0f / (1.0f + expf(-araw[i]));
        am[i] = 1.0f - s;
        ak[i] = s * kv[i];
    }

    const float4* ip = reinterpret_cast<const float4*>(inp + (size_t)warp * T_TRIALS * 3);
    float4*       op = reinterpret_cast<float4*>(out + (size_t)warp * T_TRIALS * 2);

    float sl = 0.0f, sr = 0.0f;
    const unsigned FULL = 0xFFFFFFFFu;
    const int F4_CHUNK = (256 * 3) / 4;   // 192 float4 per 256-trial chunk

    // prologue: lane's 8 trials = 24 floats = 6 aligned float4
    int f4 = 6 * lane;
    float4 v0 = ip[f4+0], v1 = ip[f4+1], v2 = ip[f4+2];
    float4 v3 = ip[f4+3], v4 = ip[f4+4], v5 = ip[f4+5];

#pragma unroll 1
    for (int chunk = 0; chunk < 8; chunk++) {
        const int t = chunk * 256 + 8 * lane;

        // per-trial (chose_left, outcome) -> affine coefficients via SEL.
        // layout per 8 trials: cl = {v0.x,v0.w,v1.z,v2.y,v3.x,v3.w,v4.z,v5.y}
        //                      oo = {v0.z,v1.y,v2.x,v2.w,v3.z,v4.y,v5.x,v5.w}
        float Al[8], Bl[8], Ar[8], Br[8];
        {
            const float clv[8] = {v0.x, v0.w, v1.z, v2.y, v3.x, v3.w, v4.z, v5.y};
            const float oov[8] = {v0.z, v1.y, v2.x, v2.w, v3.z, v4.y, v5.x, v5.w};
#pragma unroll
            for (int j = 0; j < 8; j++) {
                bool po = (oov[j] != 0.0f);
                bool pc = (clv[j] != 0.0f);
                float tA = po ? am[0] : am[1];   // "same" side
                float dA = po ? am[2] : am[3];   // "diff" side
                float tB = po ? ak[0] : ak[1];
                float dB = po ? ak[2] : ak[3];
                Al[j] = pc ? tA : dA;   Ar[j] = pc ? dA : tA;
                Bl[j] = pc ? tB : dB;   Br[j] = pc ? dB : tB;
            }
        }

        // raw input regs are free now: issue next chunk's loads (overlap scan)
        if (chunk + 1 < 8) {
            f4 += F4_CHUNK;
            v0 = ip[f4+0]; v1 = ip[f4+1]; v2 = ip[f4+2];
            v3 = ip[f4+3]; v4 = ip[f4+4]; v5 = ip[f4+5];
        }

        // compose lane's 8 trials (trial 0 first): A=A2*A1, B=A2*B1+B2
        float Acl = Al[0], Bcl = Bl[0], Acr = Ar[0], Bcr = Br[0];
#pragma unroll
        for (int j = 1; j < 8; j++) {
            Bcl = fmaf(Al[j], Bcl, Bl[j]);  Acl = Al[j] * Acl;
            Bcr = fmaf(Ar[j], Bcr, Br[j]);  Acr = Ar[j] * Acr;
        }

        // warp inclusive scan (lane 0 earliest)
#pragma unroll
        for (int d = 1; d < 32; d <<= 1) {
            float Apl = __shfl_up_sync(FULL, Acl, d);
            float Bpl = __shfl_up_sync(FULL, Bcl, d);
            float Apr = __shfl_up_sync(FULL, Acr, d);
            float Bpr = __shfl_up_sync(FULL, Bcr, d);
            if (lane >= d) {
                Bcl = fmaf(Acl, Bpl, Bcl);  Acl *= Apl;
                Bcr = fmaf(Acr, Bpr, Bcr);  Acr *= Apr;
            }
        }

        // exclusive prefix -> state entering this lane's trials
        float Ael = __shfl_up_sync(FULL, Acl, 1);
        float Bel = __shfl_up_sync(FULL, Bcl, 1);
        float Aer = __shfl_up_sync(FULL, Acr, 1);
        float Ber = __shfl_up_sync(FULL, Bcr, 1);
        if (lane == 0) { Ael = 1.0f; Bel = 0.0f; Aer = 1.0f; Ber = 0.0f; }
        float tl = fmaf(Ael, sl, Bel);
        float tr = fmaf(Aer, sr, Ber);

        // regenerate 8 per-trial outputs -> 4 aligned float4 stores
        const int ofb = (t * 2) >> 2;
#pragma unroll
        for (int h = 0; h < 4; h++) {
            float4 o;
            tl = fmaf(Al[2*h],   tl, Bl[2*h]);    tr = fmaf(Ar[2*h],   tr, Br[2*h]);
            o.x = tl;  o.y = tr;
            tl = fmaf(Al[2*h+1], tl, Bl[2*h+1]);  tr = fmaf(Ar[2*h+1], tr, Br[2*h+1]);
            o.z = tl;  o.w = tr;
            op[ofb + h] = o;
        }

        // session state = lane31's state after its last trial
        sl = __shfl_sync(FULL, tl, 31);
        sr = __shfl_sync(FULL, tr, 31);
    }
}

extern "C" void kernel_launch(void* const* d_in, const int* in_sizes, int n_in,
                              void* d_out, int out_size) {
    const float* inp  = (const float*)d_in[0];   // (4096, 2048, 3) f32
    const float* araw = (const float*)d_in[1];   // (4,) f32
    const float* kv   = (const float*)d_in[2];   // (4,) f32
    float* out = (float*)d_out;                  // (4096, 2048, 2) f32

    // 4096 warps in 128-thread blocks -> 1024 blocks
    qvalue_kernel<<<1024, 128>>>(inp, araw, kv, out);
}

// round 8
// speedup vs baseline: 1.0061x; 1.0061x over previous
#include <cuda_runtime.h>
#include <cuda_bf16.h>
#include <cstdint>
#include <math.h>

#define N_SESS   4096
#define T_TRIALS 2048
#define CHUNK    256                    // two 128-trial half-scans per chunk
#define NCHUNK   (T_TRIALS / CHUNK)     // 8
#define F4CHUNK  192                    // float4 per chunk = 256*12/16

// cp.async 16B, L2-only (streaming input, read once)
__device__ __forceinline__ void cpasync16(unsigned int dst, const float4* src) {
    asm volatile("cp.async.cg.shared.global [%0], [%1], 16;\n"
                 :: "r"(dst), "l"(src) : "memory");
}
#define CP_COMMIT() asm volatile("cp.async.commit_group;\n" ::: "memory")
#define CP_WAIT1()  asm volatile("cp.async.wait_group 1;\n" ::: "memory")

// Warp-per-session affine scan.
//  - chunk = 256 trials staged in SMEM via coalesced cp.async (double buffer)
//  - per chunk: TWO independent 128-trial warp scans (4 trials/lane each),
//    interleaved for ILP; half-B's entering state taken from half-A's lane31
//    scan composition (handoff off the regen critical path)
//  - LDS at 48B/lane stride is bank-conflict-free; stores at 32B stride
__global__ __launch_bounds__(256) void qvalue_kernel(
    const float* __restrict__ inp,    // (B, T, 3)
    const float* __restrict__ araw,   // (4,)
    const float* __restrict__ kv,     // (4,)
    float* __restrict__ out)          // (B, T, 2)
{
    __shared__ float4 sbuf[8][2][F4CHUNK];   // 49152 B

    const int tid  = threadIdx.x;
    const int wid  = tid >> 5;
    const int lane = tid & 31;
    const int warp = blockIdx.x * 8 + wid;   // 512 blocks * 8 = 4096 exactly

    // am[i] = 1 - sigmoid(araw[i]),  ak[i] = sigmoid(araw[i]) * k[i]
    float am[4], ak[4];
#pragma unroll
    for (int i = 0; i < 4; i++) {
        float s = 1.0f / (1.0f + expf(-araw[i]));
        am[i] = 1.0f - s;
        ak[i] = s * kv[i];
    }

    const float4* ip = reinterpret_cast<const float4*>(inp + (size_t)warp * T_TRIALS * 3);
    float4*       op = reinterpret_cast<float4*>(out + (size_t)warp * T_TRIALS * 2);

    const unsigned int sb_base =
        (unsigned int)__cvta_generic_to_shared(&sbuf[wid][0][0]);

    // issue one chunk's coalesced copies: 6 x 16B per lane, identity layout
    auto issue_chunk = [&](int c, int buf) {
        const float4* src = ip + c * F4CHUNK + lane;
        unsigned int dst = sb_base + (unsigned int)buf * (F4CHUNK * 16) + lane * 16;
#pragma unroll
        for (int j = 0; j < 6; j++)
            cpasync16(dst + j * 512, src + j * 32);
    };

    issue_chunk(0, 0); CP_COMMIT();
    issue_chunk(1, 1); CP_COMMIT();

    float sl = 0.0f, sr = 0.0f;
    const unsigned FULL = 0xFFFFFFFFu;

#pragma unroll 1
    for (int c = 0; c < NCHUNK; c++) {
        CP_WAIT1();          // chunk c resident (<=1 newer group pending)
        __syncwarp();

        const float4* sb = &sbuf[wid][c & 1][0];
        // half A: lane's 4 trials at float4 3*lane..; half B at 96 + 3*lane..
        float4 a0 = sb[3*lane], a1 = sb[3*lane+1], a2 = sb[3*lane+2];
        float4 b0 = sb[96+3*lane], b1 = sb[96+3*lane+1], b2 = sb[96+3*lane+2];

        // coefficients via SEL (inputs are exact {0,1})
        float AlA[4], BlA[4], ArA[4], BrA[4];
        float AlB[4], BlB[4], ArB[4], BrB[4];
        {
            const float clA[4] = {a0.x, a0.w, a1.z, a2.y};
            const float ooA[4] = {a0.z, a1.y, a2.x, a2.w};
            const float clB[4] = {b0.x, b0.w, b1.z, b2.y};
            const float ooB[4] = {b0.z, b1.y, b2.x, b2.w};
#pragma unroll
            for (int j = 0; j < 4; j++) {
                bool po = (ooA[j] != 0.0f), pc = (clA[j] != 0.0f);
                float tA = po ? am[0] : am[1], dA = po ? am[2] : am[3];
                float tB = po ? ak[0] : ak[1], dB = po ? ak[2] : ak[3];
                AlA[j] = pc ? tA : dA;  ArA[j] = pc ? dA : tA;
                BlA[j] = pc ? tB : dB;  BrA[j] = pc ? dB : tB;
            }
#pragma unroll
            for (int j = 0; j < 4; j++) {
                bool po = (ooB[j] != 0.0f), pc = (clB[j] != 0.0f);
                float tA = po ? am[0] : am[1], dA = po ? am[2] : am[3];
                float tB = po ? ak[0] : ak[1], dB = po ? ak[2] : ak[3];
                AlB[j] = pc ? tA : dA;  ArB[j] = pc ? dA : tA;
                BlB[j] = pc ? tB : dB;  BrB[j] = pc ? dB : tB;
            }
        }

        // buffer consumed -> refill it with chunk c+2 (loads fly during scan)
        if (c + 2 < NCHUNK) issue_chunk(c + 2, c & 1);
        CP_COMMIT();   // always commit (keeps wait_group bookkeeping simple)

        // per-lane composition, both halves (trial 0 first)
        float AclA = AlA[0], BclA = BlA[0], AcrA = ArA[0], BcrA = BrA[0];
        float AclB = AlB[0], BclB = BlB[0], AcrB = ArB[0], BcrB = BrB[0];
#pragma unroll
        for (int j = 1; j < 4; j++) {
            BclA = fmaf(AlA[j], BclA, BlA[j]);  AclA = AlA[j] * AclA;
            BcrA = fmaf(ArA[j], BcrA, BrA[j]);  AcrA = ArA[j] * AcrA;
            BclB = fmaf(AlB[j], BclB, BlB[j]);  AclB = AlB[j] * AclB;
            BcrB = fmaf(ArB[j], BcrB, BrB[j]);  AcrB = ArB[j] * AcrB;
        }

        // two interleaved 5-level inclusive warp scans
#pragma unroll
        for (int d = 1; d < 32; d <<= 1) {
            float pAlA = __shfl_up_sync(FULL, AclA, d);
            float pBlA = __shfl_up_sync(FULL, BclA, d);
            float pArA = __shfl_up_sync(FULL, AcrA, d);
            float pBrA = __shfl_up_sync(FULL, BcrA, d);
            float pAlB = __shfl_up_sync(FULL, AclB, d);
            float pBlB = __shfl_up_sync(FULL, BclB, d);
            float pArB = __shfl_up_sync(FULL, AcrB, d);
            float pBrB = __shfl_up_sync(FULL, BcrB, d);
            if (lane >= d) {
                BclA = fmaf(AclA, pBlA, BclA);  AclA *= pAlA;
                BcrA = fmaf(AcrA, pBrA, BcrA);  AcrA *= pArA;
                BclB = fmaf(AclB, pBlB, BclB);  AclB *= pAlB;
                BcrB = fmaf(AcrB, pBrB, BcrB);  AcrB *= pArB;
            }
        }

        // half-A entering states (exclusive prefix applied to session state)
        float AeA_l = __shfl_up_sync(FULL, AclA, 1);
        float BeA_l = __shfl_up_sync(FULL, BclA, 1);
        float AeA_r = __shfl_up_sync(FULL, AcrA, 1);
        float BeA_r = __shfl_up_sync(FULL, BcrA, 1);
        // half-B entering session state from half-A lane31 composition
        float A31l = __shfl_sync(FULL, AclA, 31);
        float B31l = __shfl_sync(FULL, BclA, 31);
        float A31r = __shfl_sync(FULL, AcrA, 31);
        float B31r = __shfl_sync(FULL, BcrA, 31);
        float sBl = fmaf(A31l, sl, B31l);
        float sBr = fmaf(A31r, sr, B31r);

        float AeB_l = __shfl_up_sync(FULL, AclB, 1);
        float BeB_l = __shfl_up_sync(FULL, BclB, 1);
        float AeB_r = __shfl_up_sync(FULL, AcrB, 1);
        float BeB_r = __shfl_up_sync(FULL, BcrB, 1);
        if (lane == 0) {
            AeA_l = 1.0f; BeA_l = 0.0f;  AeA_r = 1.0f; BeA_r = 0.0f;
            AeB_l = 1.0f; BeB_l = 0.0f;  AeB_r = 1.0f; BeB_r = 0.0f;
        }
        float tlA = fmaf(AeA_l, sl,  BeA_l);
        float trA = fmaf(AeA_r, sr,  BeA_r);
        float tlB = fmaf(AeB_l, sBl, BeB_l);
        float trB = fmaf(AeB_r, sBr, BeB_r);

        // next session state from half-B lane31 composition
        {
            float A31bl = __shfl_sync(FULL, AclB, 31);
            float B31bl = __shfl_sync(FULL, BclB, 31);
            float A31br = __shfl_sync(FULL, AcrB, 31);
            float B31br = __shfl_sync(FULL, BcrB, 31);
            sl = fmaf(A31bl, sBl, B31bl);
            sr = fmaf(A31br, sBr, B31br);
        }

        // regenerate per-trial outputs, both halves (2 float4 stores each)
        const int ofbA = c * 128 + 2 * lane;        // float4 index into (T,2)
        const int ofbB = ofbA + 64;
        float4 oA0, oA1, oB0, oB1;
        tlA = fmaf(AlA[0], tlA, BlA[0]);  trA = fmaf(ArA[0], trA, BrA[0]);
        oA0.x = tlA;  oA0.y = trA;
        tlA = fmaf(AlA[1], tlA, BlA[1]);  trA = fmaf(ArA[1], trA, BrA[1]);
        oA0.z = tlA;  oA0.w = trA;
        tlA = fmaf(AlA[2], tlA, BlA[2]);  trA = fmaf(ArA[2], trA, BrA[2]);
        oA1.x = tlA;  oA1.y = trA;
        tlA = fmaf(AlA[3], tlA, BlA[3]);  trA = fmaf(ArA[3], trA, BrA[3]);
        oA1.z = tlA;  oA1.w = trA;

        tlB = fmaf(AlB[0], tlB, BlB[0]);  trB = fmaf(ArB[0], trB, BrB[0]);
        oB0.x = tlB;  oB0.y = trB;
        tlB = fmaf(AlB[1], tlB, BlB[1]);  trB = fmaf(ArB[1], trB, BrB[1]);
        oB0.z = tlB;  oB0.w = trB;
        tlB = fmaf(AlB[2], tlB, BlB[2]);  trB = fmaf(ArB[2], trB, BrB[2]);
        oB1.x = tlB;  oB1.y = trB;
        tlB = fmaf(AlB[3], tlB, BlB[3]);  trB = fmaf(ArB[3], trB, BrB[3]);
        oB1.z = tlB;  oB1.w = trB;

        op[ofbA]     = oA0;
        op[ofbA + 1] = oA1;
        op[ofbB]     = oB0;
        op[ofbB + 1] = oB1;
    }
}

extern "C" void kernel_launch(void* const* d_in, const int* in_sizes, int n_in,
                              void* d_out, int out_size) {
    const float* inp  = (const float*)d_in[0];   // (4096, 2048, 3) f32
    const float* araw = (const float*)d_in[1];   // (4,) f32
    const float* kv   = (const float*)d_in[2];   // (4,) f32
    float* out = (float*)d_out;                  // (4096, 2048, 2) f32

    // 4096 warps: 512 blocks x 256 threads (8 warps/block)
    qvalue_kernel<<<512, 256>>>(inp, araw, kv, out);
}